// round 17
// baseline (speedup 1.0000x reference)
#include <cuda_runtime.h>
#include <cuda_bf16.h>
#include <cstdint>

// Problem constants
#define Nn     50000
#define Dd     64
#define Ee     800000
#define Bb     50
#define NMAXx  1000
#define Cc     100

// ---------------------------------------------------------------------------
// Device scratch (no allocations allowed)
// ---------------------------------------------------------------------------
__device__ float g_xa[Nn * Dd];          // x @ W_ma[:64] + b_ma
__device__ float g_acc[Nn * Dd];         // (1+eps1)*x + segment_sum(msg)
__device__ float g_up[Nn * Dd];          // einsum result (flat [B*NMAX, D])

// W_ma split n-major: first-half (node branch) and second-half (edge branch)
__device__ unsigned short g_Wn[2 * 4096];    // [W1_h, W1_l]
__device__ unsigned short g_Wbhi[64 * 64];
__device__ unsigned short g_Wblo[64 * 64];

// W_mu split n-major (mlp branch)
__device__ unsigned short g_Wmu[2 * 4096];

// k_final weights: 8 tiles n-major
__device__ unsigned short g_Wf[8 * 4096];

// msgup split for upagg B operand: [b][n][112] (k zero-padded 100->112)
__device__ unsigned short g_msgupBh[Bb * 64 * 112];
__device__ unsigned short g_msgupBl[Bb * 64 * 112];

// ---------------------------------------------------------------------------
// mma.sync / ldmatrix helpers (base ISA, sm_80+)
// ---------------------------------------------------------------------------
__device__ __forceinline__ uint32_t smem_u32(const void* p) {
    uint32_t a;
    asm("{ .reg .u64 t; cvta.to.shared.u64 t, %1; cvt.u32.u64 %0, t; }"
        : "=r"(a) : "l"(p));
    return a;
}
__device__ __forceinline__ void ldsm_x4(uint32_t* r, uint32_t addr) {
    asm volatile("ldmatrix.sync.aligned.m8n8.x4.shared.b16 {%0,%1,%2,%3}, [%4];"
                 : "=r"(r[0]), "=r"(r[1]), "=r"(r[2]), "=r"(r[3]) : "r"(addr));
}
__device__ __forceinline__ void ldsm_x2(uint32_t* r, uint32_t addr) {
    asm volatile("ldmatrix.sync.aligned.m8n8.x2.shared.b16 {%0,%1}, [%2];"
                 : "=r"(r[0]), "=r"(r[1]) : "r"(addr));
}
__device__ __forceinline__ void mma_bf16(float* c, const uint32_t* a,
                                         const uint32_t* b) {
    asm volatile(
        "mma.sync.aligned.m16n8k16.row.col.f32.bf16.bf16.f32 "
        "{%0,%1,%2,%3}, {%4,%5,%6,%7}, {%8,%9}, {%0,%1,%2,%3};"
        : "+f"(c[0]), "+f"(c[1]), "+f"(c[2]), "+f"(c[3])
        : "r"(a[0]), "r"(a[1]), "r"(a[2]), "r"(a[3]), "r"(b[0]), "r"(b[1]));
}
__device__ __forceinline__ void red_add_v4(float* p, float a, float b,
                                           float c, float d) {
    asm volatile("red.global.add.v4.f32 [%0], {%1, %2, %3, %4};"
                 :: "l"(p), "f"(a), "f"(b), "f"(c), "f"(d) : "memory");
}
__device__ __forceinline__ void split_hl(float w, unsigned short& hi,
                                         unsigned short& lo) {
    uint32_t u = __float_as_uint(w);
    hi = (unsigned short)(u >> 16);
    float l = w - __uint_as_float(u & 0xFFFF0000u);
    lo = __bfloat16_as_ushort(__float2bfloat16(l));
}
// split float4 -> hi-pair / lo-pair words
__device__ __forceinline__ void split4(float4 v, uint2& hi, uint2& lo) {
    uint32_t u0 = __float_as_uint(v.x), u1 = __float_as_uint(v.y);
    uint32_t u2 = __float_as_uint(v.z), u3 = __float_as_uint(v.w);
    hi.x = (u0 >> 16) | (u1 & 0xFFFF0000u);
    hi.y = (u2 >> 16) | (u3 & 0xFFFF0000u);
    float l0 = v.x - __uint_as_float(u0 & 0xFFFF0000u);
    float l1 = v.y - __uint_as_float(u1 & 0xFFFF0000u);
    float l2 = v.z - __uint_as_float(u2 & 0xFFFF0000u);
    float l3 = v.w - __uint_as_float(u3 & 0xFFFF0000u);
    __nv_bfloat162 p01 = __floats2bfloat162_rn(l0, l1);
    __nv_bfloat162 p23 = __floats2bfloat162_rn(l2, l3);
    lo.x = *(uint32_t*)&p01;
    lo.y = *(uint32_t*)&p23;
}

// ---------------------------------------------------------------------------
// Merged prep: all weight splits + zero msgupB k-padding.
// ---------------------------------------------------------------------------
__global__ void k_prep_all(const float* __restrict__ W_ma,
                           const float* __restrict__ W_ua,
                           const float* __restrict__ W_uu,
                           const float* __restrict__ W_c,
                           const float* __restrict__ W_mu) {
    int i = blockIdx.x * 256 + threadIdx.x;
    unsigned short h, l;
    if (i < 128 * 64) {
        int k = i >> 6, n = i & 63;
        split_hl(W_ma[k * 64 + n], h, l);
        if (k < 64) {
            g_Wn[0 * 4096 + n * 64 + k] = h;
            g_Wn[1 * 4096 + n * 64 + k] = l;
        } else {
            g_Wbhi[n * 64 + (k - 64)] = h;
            g_Wblo[n * 64 + (k - 64)] = l;
        }
    }
    if (i < 4096) {
        int k = i >> 6, n = i & 63;
        split_hl(W_ua[k * 64 + n], h, l);
        g_Wf[0 * 4096 + n * 64 + k] = h;
        g_Wf[1 * 4096 + n * 64 + k] = l;
        split_hl(W_uu[k * 64 + n], h, l);
        g_Wf[2 * 4096 + n * 64 + k] = h;
        g_Wf[3 * 4096 + n * 64 + k] = l;
        split_hl(W_c[k * 64 + n], h, l);
        g_Wf[4 * 4096 + n * 64 + k] = h;
        g_Wf[5 * 4096 + n * 64 + k] = l;
        split_hl(W_c[(64 + k) * 64 + n], h, l);
        g_Wf[6 * 4096 + n * 64 + k] = h;
        g_Wf[7 * 4096 + n * 64 + k] = l;
        split_hl(W_mu[k * 64 + n], h, l);
        g_Wmu[0 * 4096 + n * 64 + k] = h;
        g_Wmu[1 * 4096 + n * 64 + k] = l;
    }
    if (i < Bb * 64 * 12) {
        int b = i / (64 * 12);
        int rem = i % (64 * 12);
        int n = rem / 12;
        int c = 100 + rem % 12;
        size_t idx = ((size_t)b * 64 + n) * 112 + c;
        g_msgupBh[idx] = 0;
        g_msgupBl[idx] = 0;
    }
}

// ---------------------------------------------------------------------------
// Fat kernel 1: node_pre path (blocks 0..390) + mlp path (391..430).
// ---------------------------------------------------------------------------
#define NODE_BLKS 391
#define MLP_BLKS  40
#define NP_HI 0
#define NP_LO 18432
#define NP_B  36864
#define NP_BIAS 55296
#define SM_NP_TOT 55552

__global__ __launch_bounds__(256) void k_pre_fused(
    const float* __restrict__ x, const float* __restrict__ eps1,
    const float* __restrict__ b_ma,
    const float* __restrict__ attr1, const float* __restrict__ b_mu)
{
    extern __shared__ char smc[];
    const uint32_t sbase = smem_u32(smc);
    float* bias = (float*)(smc + NP_BIAS);
    const int t = threadIdx.x;
    const int w = t >> 5;
    const int lane = t & 31;

    const bool is_node = (blockIdx.x < NODE_BLKS);

    const int arow = 16 * w + (lane & 15);
    const int acolB = ((lane >> 4) * 8) * 2;
    const int bl = lane & 15;
    const int brow = bl & 7;
    const int bkB = ((bl >> 3) * 8) * 2;
    const int grp = lane >> 2, tig = lane & 3;
    const int myrow = 16 * w + grp;

    if (is_node) {
        const int row0 = blockIdx.x * 128;
        {
            const uint4* srcW = (const uint4*)g_Wn;
#pragma unroll
            for (int i = t; i < 1024; i += 256) {
                int tile = i >> 9;
                int j = i & 511;
                int r = j >> 3, c = j & 7;
                *(uint4*)(smc + NP_B + tile * 9216 + r * 144 + c * 16) = srcW[i];
            }
        }
        if (t < 64) bias[t] = b_ma[t];
        const float e1 = 1.0f + eps1[0];

#pragma unroll
        for (int i = t; i < 2048; i += 256) {
            int r = i >> 4, q = i & 15;
            int gr0 = row0 + r;
            int gr = min(gr0, Nn - 1);
            float4 v = *(const float4*)(x + (size_t)gr * 64 + q * 4);
            if (gr0 < Nn) {
                float4 av = make_float4(e1 * v.x, e1 * v.y, e1 * v.z, e1 * v.w);
                *(float4*)(g_acc + (size_t)gr0 * 64 + q * 4) = av;
            }
            uint2 hi, lo;
            split4(v, hi, lo);
            *(uint2*)(smc + NP_HI + r * 144 + q * 8) = hi;
            *(uint2*)(smc + NP_LO + r * 144 + q * 8) = lo;
        }
        __syncthreads();

        uint32_t ah[4][4], al[4][4];
#pragma unroll
        for (int kt = 0; kt < 4; kt++) {
            uint32_t off = (uint32_t)(arow * 144 + kt * 32 + acolB);
            ldsm_x4(ah[kt], sbase + NP_HI + off);
            ldsm_x4(al[kt], sbase + NP_LO + off);
        }

#pragma unroll
        for (int nt = 0; nt < 8; nt++) {
            uint32_t bh[4][2], blv[4][2];
#pragma unroll
            for (int kt = 0; kt < 4; kt++) {
                uint32_t ba = (uint32_t)((nt * 8 + brow) * 144 + kt * 32 + bkB);
                ldsm_x2(bh[kt],  sbase + NP_B + 0 * 9216 + ba);
                ldsm_x2(blv[kt], sbase + NP_B + 1 * 9216 + ba);
            }
            float c[4] = {0.f, 0.f, 0.f, 0.f};
#pragma unroll
            for (int kt = 0; kt < 4; kt++) {
                mma_bf16(c, ah[kt], bh[kt]);
                mma_bf16(c, ah[kt], blv[kt]);
                mma_bf16(c, al[kt], bh[kt]);
            }
            int col = nt * 8 + 2 * tig;
            int gr1 = row0 + myrow;
            int gr2 = gr1 + 8;
            if (gr1 < Nn)
                *(float2*)(g_xa + (size_t)gr1 * 64 + col) =
                    make_float2(c[0] + bias[col], c[1] + bias[col + 1]);
            if (gr2 < Nn)
                *(float2*)(g_xa + (size_t)gr2 * 64 + col) =
                    make_float2(c[2] + bias[col], c[3] + bias[col + 1]);
        }
    } else {
        const int row0 = (blockIdx.x - NODE_BLKS) * 128;
        const int M = Bb * Cc;   // 5000
        {
            const uint4* srcW = (const uint4*)g_Wmu;
#pragma unroll
            for (int i = t; i < 1024; i += 256) {
                int tile = i >> 9;
                int j = i & 511;
                int r = j >> 3, c = j & 7;
                *(uint4*)(smc + NP_B + tile * 9216 + r * 144 + c * 16) = srcW[i];
            }
        }
        if (t < 64) bias[t] = b_mu[t];

#pragma unroll
        for (int i = t; i < 2048; i += 256) {
            int r = i >> 4, q = i & 15;
            int m = min(row0 + r, M - 1);
            float4 v = *(const float4*)(attr1 + (size_t)m * 64 + q * 4);
            uint2 hi, lo;
            split4(v, hi, lo);
            *(uint2*)(smc + NP_HI + r * 144 + q * 8) = hi;
            *(uint2*)(smc + NP_LO + r * 144 + q * 8) = lo;
        }
        __syncthreads();

        uint32_t ah[4][4], al[4][4];
#pragma unroll
        for (int kt = 0; kt < 4; kt++) {
            uint32_t off = (uint32_t)(arow * 144 + kt * 32 + acolB);
            ldsm_x4(ah[kt], sbase + NP_HI + off);
            ldsm_x4(al[kt], sbase + NP_LO + off);
        }

#pragma unroll
        for (int nt = 0; nt < 8; nt++) {
            uint32_t bh[4][2], blv[4][2];
#pragma unroll
            for (int kt = 0; kt < 4; kt++) {
                uint32_t ba = (uint32_t)((nt * 8 + brow) * 144 + kt * 32 + bkB);
                ldsm_x2(bh[kt],  sbase + NP_B + 0 * 9216 + ba);
                ldsm_x2(blv[kt], sbase + NP_B + 1 * 9216 + ba);
            }
            float c[4] = {0.f, 0.f, 0.f, 0.f};
#pragma unroll
            for (int kt = 0; kt < 4; kt++) {
                mma_bf16(c, ah[kt], bh[kt]);
                mma_bf16(c, ah[kt], blv[kt]);
                mma_bf16(c, al[kt], bh[kt]);
            }
            int col = nt * 8 + 2 * tig;
            int m1 = row0 + myrow;
            int m2 = m1 + 8;
            if (m1 < M) {
                int b = m1 / Cc, cc = m1 % Cc;
                unsigned short h, l;
                split_hl(fmaxf(c[0] + bias[col], 0.f), h, l);
                size_t i0 = ((size_t)b * 64 + col) * 112 + cc;
                g_msgupBh[i0] = h; g_msgupBl[i0] = l;
                split_hl(fmaxf(c[1] + bias[col + 1], 0.f), h, l);
                size_t i1 = ((size_t)b * 64 + col + 1) * 112 + cc;
                g_msgupBh[i1] = h; g_msgupBl[i1] = l;
            }
            if (m2 < M) {
                int b = m2 / Cc, cc = m2 % Cc;
                unsigned short h, l;
                split_hl(fmaxf(c[2] + bias[col], 0.f), h, l);
                size_t i0 = ((size_t)b * 64 + col) * 112 + cc;
                g_msgupBh[i0] = h; g_msgupBl[i0] = l;
                split_hl(fmaxf(c[3] + bias[col + 1], 0.f), h, l);
                size_t i1 = ((size_t)b * 64 + col + 1) * 112 + cc;
                g_msgupBh[i1] = h; g_msgupBl[i1] = l;
            }
        }
    }
}

// ---------------------------------------------------------------------------
// Kernel 3 (HMMA): g_up[b,n,:] = sum_c nc1[b,n,c] * msgup[b,c,:]
// ---------------------------------------------------------------------------
#define UP_AHI 0
#define UP_ALO 30720
#define UP_BHI 61440
#define UP_BLO 76800
#define SM_UPG_TOT 92160

__global__ __launch_bounds__(256) void k_upagg_hmma(const float* __restrict__ nc1)
{
    extern __shared__ char smc[];
    const uint32_t sbase = smem_u32(smc);
    const int t = threadIdx.x;
    const int w = t >> 5;
    const int lane = t & 31;
    const int b = blockIdx.y;
    const int row0 = blockIdx.x * 128;

#pragma unroll
    for (int i = t; i < 896; i += 256) {
        int r = i / 14, c = i % 14;
        size_t src = ((size_t)b * 64 + r) * 112 + c * 8;
        *(uint4*)(smc + UP_BHI + r * 240 + c * 16) = *(const uint4*)(g_msgupBh + src);
        *(uint4*)(smc + UP_BLO + r * 240 + c * 16) = *(const uint4*)(g_msgupBl + src);
    }

#pragma unroll
    for (int i = t; i < 3200; i += 256) {
        int r = i / 25, j = i % 25;
        int gr = min(row0 + r, NMAXx - 1);
        float4 v = *(const float4*)(nc1 + ((size_t)b * NMAXx + gr) * Cc + j * 4);
        uint2 hi, lo;
        split4(v, hi, lo);
        *(uint2*)(smc + UP_AHI + r * 240 + j * 8) = hi;
        *(uint2*)(smc + UP_ALO + r * 240 + j * 8) = lo;
    }
#pragma unroll
    for (int i = t; i < 384; i += 256) {
        int r = i / 3, j = i % 3;
        *(uint2*)(smc + UP_AHI + r * 240 + 200 + j * 8) = make_uint2(0u, 0u);
        *(uint2*)(smc + UP_ALO + r * 240 + 200 + j * 8) = make_uint2(0u, 0u);
    }
    __syncthreads();

    const int arow = 16 * w + (lane & 15);
    const int acolB = ((lane >> 4) * 8) * 2;
    const int bl = lane & 15;
    const int brow = bl & 7;
    const int bkB = ((bl >> 3) * 8) * 2;
    const int grp = lane >> 2, tig = lane & 3;
    const int myrow = 16 * w + grp;

    uint32_t ah[7][4], al[7][4];
#pragma unroll
    for (int kt = 0; kt < 7; kt++) {
        uint32_t off = (uint32_t)(arow * 240 + kt * 32 + acolB);
        ldsm_x4(ah[kt], sbase + UP_AHI + off);
        ldsm_x4(al[kt], sbase + UP_ALO + off);
    }

#pragma unroll
    for (int nt = 0; nt < 8; nt++) {
        float c[4] = {0.f, 0.f, 0.f, 0.f};
#pragma unroll
        for (int kt = 0; kt < 7; kt++) {
            uint32_t ba = (uint32_t)((nt * 8 + brow) * 240 + kt * 32 + bkB);
            uint32_t bh[2], blv[2];
            ldsm_x2(bh,  sbase + UP_BHI + ba);
            ldsm_x2(blv, sbase + UP_BLO + ba);
            mma_bf16(c, ah[kt], bh);
            mma_bf16(c, ah[kt], blv);
            mma_bf16(c, al[kt], bh);
        }
        int col = nt * 8 + 2 * tig;
        int gr1 = row0 + myrow;
        int gr2 = gr1 + 8;
        if (gr1 < NMAXx)
            *(float2*)(g_up + ((size_t)b * NMAXx + gr1) * 64 + col) =
                make_float2(c[0], c[1]);
        if (gr2 < NMAXx)
            *(float2*)(g_up + ((size_t)b * NMAXx + gr2) * 64 + col) =
                make_float2(c[2], c[3]);
    }
}

// ---------------------------------------------------------------------------
// Kernel 4: split-bf16 HMMA edge kernel, M-tile = 256 edges/CTA.
// Each warp owns 32 edge rows (2 m16 fragments). B hi/lo fragments fetched
// with ONE ldmatrix.x4 (lanes 0-15 -> BHI, lanes 16-31 -> BLO).
// Cstage [256][68] f32 overlays the A region after fragment preload.
// ---------------------------------------------------------------------------
#define SMA_HI 0
#define SMA_LO 36864
#define SMB_HI 73728
#define SMB_LO 82944
#define SM_EDGE_TOT 92160

__global__ __launch_bounds__(256, 2) void k_edge_hmma(
    const float* __restrict__ e, const int* __restrict__ ei)
{
    extern __shared__ char smc[];
    const uint32_t sbase = smem_u32(smc);
    const int t = threadIdx.x;
    const int w = t >> 5;
    const int lane = t & 31;
    const int e0 = blockIdx.x * 256;

    // B tiles: bf16 n-major, stride-144B rows
    {
        const uint4* srcH = (const uint4*)g_Wbhi;
        const uint4* srcL = (const uint4*)g_Wblo;
#pragma unroll
        for (int i = t; i < 512; i += 256) {
            int r = i >> 3, c = i & 7;
            *(uint4*)(smc + SMB_HI + r * 144 + c * 16) = srcH[i];
            *(uint4*)(smc + SMB_LO + r * 144 + c * 16) = srcL[i];
        }
    }

    // A tile: 256 e rows, split fp32 -> bf16 hi/lo
#pragma unroll
    for (int i = t; i < 4096; i += 256) {
        int r = i >> 4, q = i & 15;
        float4 v = *(const float4*)(e + (size_t)(e0 + r) * 64 + q * 4);
        uint2 hi, lo;
        split4(v, hi, lo);
        *(uint2*)(smc + SMA_HI + r * 144 + q * 8) = hi;
        *(uint2*)(smc + SMA_LO + r * 144 + q * 8) = lo;
    }
    __syncthreads();

    // Preload A fragments: 2 m-tiles x 4 k-tiles, hi+lo (64 regs)
    uint32_t ah[2][4][4], al[2][4][4];
    {
        int acolB = ((lane >> 4) * 8) * 2;
#pragma unroll
        for (int mt = 0; mt < 2; mt++) {
            int arow = 32 * w + 16 * mt + (lane & 15);
#pragma unroll
            for (int kt = 0; kt < 4; kt++) {
                uint32_t off = (uint32_t)(arow * 144 + kt * 32 + acolB);
                ldsm_x4(ah[mt][kt], sbase + SMA_HI + off);
                ldsm_x4(al[mt][kt], sbase + SMA_LO + off);
            }
        }
    }
    __syncthreads();   // A consumed -> Cstage may overlay [0, 69632)

    float* cst = (float*)smc;   // Cstage [256][68]

    // merged B addressing: lanes 0-15 -> BHI rows, lanes 16-31 -> BLO rows
    const int bl = lane & 15;
    const int brow = bl & 7;
    const int bkB = ((bl >> 3) * 8) * 2;
    const uint32_t bbase = sbase + ((lane < 16) ? SMB_HI : SMB_LO);
    const int grp = lane >> 2, tig = lane & 3;

#pragma unroll
    for (int nt = 0; nt < 8; nt++) {
        uint32_t bb[4][4];   // [kt][0..1]=hi frag, [2..3]=lo frag
#pragma unroll
        for (int kt = 0; kt < 4; kt++) {
            uint32_t ba = bbase + (uint32_t)((nt * 8 + brow) * 144 + kt * 32 + bkB);
            ldsm_x4(bb[kt], ba);
        }
        float c0[4] = {0.f, 0.f, 0.f, 0.f};
        float c1[4] = {0.f, 0.f, 0.f, 0.f};
#pragma unroll
        for (int kt = 0; kt < 4; kt++) {
            mma_bf16(c0, ah[0][kt], bb[kt]);       // Ah*Bh
            mma_bf16(c0, ah[0][kt], bb[kt] + 2);   // Ah*Bl
            mma_bf16(c0, al[0][kt], bb[kt]);       // Al*Bh
            mma_bf16(c1, ah[1][kt], bb[kt]);
            mma_bf16(c1, ah[1][kt], bb[kt] + 2);
            mma_bf16(c1, al[1][kt], bb[kt]);
        }
        int col = nt * 8 + 2 * tig;
        int row = 32 * w + grp;
        *(float2*)(cst + row * 68 + col)        = make_float2(c0[0], c0[1]);
        *(float2*)(cst + (row + 8) * 68 + col)  = make_float2(c0[2], c0[3]);
        *(float2*)(cst + (row + 16) * 68 + col) = make_float2(c1[0], c1[1]);
        *(float2*)(cst + (row + 24) * 68 + col) = make_float2(c1[2], c1[3]);
    }
    __syncthreads();

    // Epilogue: thread owns 16 rows x 4 cols; one red.v4 per (row, col-quad).
    {
        const int r0 = (t / 16) * 16, c0 = (t % 16) * 4;
        const int* __restrict__ srcp = ei;
        const int* __restrict__ dstp = ei + Ee;
#pragma unroll
        for (int i = 0; i < 16; i++) {
            int er = e0 + r0 + i;
            int s = srcp[er];
            int d = dstp[er];
            float4 xa = *(const float4*)(g_xa + (size_t)s * 64 + c0);
            float4 cw = *(const float4*)(cst + (r0 + i) * 68 + c0);
            float m0 = fmaxf(cw.x + xa.x, 0.f);
            float m1 = fmaxf(cw.y + xa.y, 0.f);
            float m2 = fmaxf(cw.z + xa.z, 0.f);
            float m3 = fmaxf(cw.w + xa.w, 0.f);
            red_add_v4(g_acc + (size_t)d * 64 + c0, m0, m1, m2, m3);
        }
    }
}

// ---------------------------------------------------------------------------
// Kernel 5: HMMA fused tail (unchanged).
// ---------------------------------------------------------------------------
#define FA_HI 0
#define FA_LO 18432
#define FB_BASE 36864
#define FBIAS 110592
#define SM_FIN_TOT 111360

__global__ __launch_bounds__(256) void k_final_hmma(
    const float* __restrict__ x, const int* __restrict__ x_idx,
    const float* __restrict__ eps2,
    const float* __restrict__ b_ua, const float* __restrict__ b_uu,
    const float* __restrict__ b_c, float* __restrict__ out)
{
    extern __shared__ char smc[];
    const uint32_t sbase = smem_u32(smc);
    float* bias = (float*)(smc + FBIAS);
    const int t = threadIdx.x;
    const int w = t >> 5;
    const int lane = t & 31;
    const int row0 = blockIdx.x * 128;
    const float e2v = 1.0f + eps2[0];

    {
        const uint4* srcW = (const uint4*)g_Wf;
#pragma unroll
        for (int i = t; i < 4096; i += 256) {
            int tile = i >> 9;
            int j = i & 511;
            int r = j >> 3, c = j & 7;
            *(uint4*)(smc + FB_BASE + tile * 9216 + r * 144 + c * 16) = srcW[i];
        }
    }
    if (t < 64) {
        bias[t] = b_ua[t];
        bias[64 + t] = b_uu[t];
        bias[128 + t] = b_c[t];
    }

#pragma unroll
    for (int i = t; i < 2048; i += 256) {
        int r = i >> 4, q = i & 15;
        int gr = min(row0 + r, Nn - 1);
        float4 v = *(const float4*)(g_acc + (size_t)gr * 64 + q * 4);
        uint2 hi, lo;
        split4(v, hi, lo);
        *(uint2*)(smc + FA_HI + r * 144 + q * 8) = hi;
        *(uint2*)(smc + FA_LO + r * 144 + q * 8) = lo;
    }
    __syncthreads();

    const int arow = 16 * w + (lane & 15);
    const int acolB = ((lane >> 4) * 8) * 2;
    const int bl = lane & 15;
    const int brow = bl & 7;
    const int bkB = ((bl >> 3) * 8) * 2;
    const int grp = lane >> 2, tig = lane & 3;
    const int myrow = 16 * w + grp;

    uint32_t a1h[4][4], a1l[4][4];
#pragma unroll
    for (int kt = 0; kt < 4; kt++) {
        uint32_t off = (uint32_t)(arow * 144 + kt * 32 + acolB);
        ldsm_x4(a1h[kt], sbase + FA_HI + off);
        ldsm_x4(a1l[kt], sbase + FA_LO + off);
    }
    __syncthreads();

#pragma unroll
    for (int i = t; i < 2048; i += 256) {
        int r = i >> 4, q = i & 15;
        int gr = min(row0 + r, Nn - 1);
        int xi = x_idx[gr];
        float4 u = *(const float4*)(g_up + (size_t)xi * 64 + q * 4);
        float4 xv = *(const float4*)(x + (size_t)gr * 64 + q * 4);
        float4 v = make_float4(u.x + e2v * xv.x, u.y + e2v * xv.y,
                               u.z + e2v * xv.z, u.w + e2v * xv.w);
        uint2 hi, lo;
        split4(v, hi, lo);
        *(uint2*)(smc + FA_HI + r * 144 + q * 8) = hi;
        *(uint2*)(smc + FA_LO + r * 144 + q * 8) = lo;
    }
    __syncthreads();

    uint32_t a2h[4][4], a2l[4][4];
#pragma unroll
    for (int kt = 0; kt < 4; kt++) {
        uint32_t off = (uint32_t)(arow * 144 + kt * 32 + acolB);
        ldsm_x4(a2h[kt], sbase + FA_HI + off);
        ldsm_x4(a2l[kt], sbase + FA_LO + off);
    }
    __syncthreads();

    // Phase 1a: h1 = relu(A1@Wua + bua) -> split -> FA
#pragma unroll
    for (int nt = 0; nt < 8; nt++) {
        uint32_t bh[4][2], blv[4][2];
#pragma unroll
        for (int kt = 0; kt < 4; kt++) {
            uint32_t ba = (uint32_t)((nt * 8 + brow) * 144 + kt * 32 + bkB);
            ldsm_x2(bh[kt],  sbase + FB_BASE + 0 * 9216 + ba);
            ldsm_x2(blv[kt], sbase + FB_BASE + 1 * 9216 + ba);
        }
        float c[4] = {0.f, 0.f, 0.f, 0.f};
#pragma unroll
        for (int kt = 0; kt < 4; kt++) {
            mma_bf16(c, a1h[kt], bh[kt]);
            mma_bf16(c, a1h[kt], blv[kt]);
            mma_bf16(c, a1l[kt], bh[kt]);
        }
        int col = nt * 8 + 2 * tig;
        float h0 = fmaxf(c[0] + bias[col], 0.f);
        float h1v = fmaxf(c[1] + bias[col + 1], 0.f);
        float h2v = fmaxf(c[2] + bias[col], 0.f);
        float h3v = fmaxf(c[3] + bias[col + 1], 0.f);
        uint2 hiA, loA;
        split4(make_float4(h0, h1v, h2v, h3v), hiA, loA);
        *(uint32_t*)(smc + FA_HI + myrow * 144 + col * 2) = hiA.x;
        *(uint32_t*)(smc + FA_LO + myrow * 144 + col * 2) = loA.x;
        *(uint32_t*)(smc + FA_HI + (myrow + 8) * 144 + col * 2) = hiA.y;
        *(uint32_t*)(smc + FA_LO + (myrow + 8) * 144 + col * 2) = loA.y;
    }
    __syncthreads();

#pragma unroll
    for (int kt = 0; kt < 4; kt++) {
        uint32_t off = (uint32_t)(arow * 144 + kt * 32 + acolB);
        ldsm_x4(a1h[kt], sbase + FA_HI + off);
        ldsm_x4(a1l[kt], sbase + FA_LO + off);
    }
    __syncthreads();

    // Phase 1b: h2 = relu(A2@Wuu + buu) -> split -> FA
#pragma unroll
    for (int nt = 0; nt < 8; nt++) {
        uint32_t bh[4][2], blv[4][2];
#pragma unroll
        for (int kt = 0; kt < 4; kt++) {
            uint32_t ba = (uint32_t)((nt * 8 + brow) * 144 + kt * 32 + bkB);
            ldsm_x2(bh[kt],  sbase + FB_BASE + 2 * 9216 + ba);
            ldsm_x2(blv[kt], sbase + FB_BASE + 3 * 9216 + ba);
        }
        float c[4] = {0.f, 0.f, 0.f, 0.f};
#pragma unroll
        for (int kt = 0; kt < 4; kt++) {
            mma_bf16(c, a2h[kt], bh[kt]);
            mma_bf16(c, a2h[kt], blv[kt]);
            mma_bf16(c, a2l[kt], bh[kt]);
        }
        int col = nt * 8 + 2 * tig;
        float h0 = fmaxf(c[0] + bias[64 + col], 0.f);
        float h1v = fmaxf(c[1] + bias[64 + col + 1], 0.f);
        float h2v = fmaxf(c[2] + bias[64 + col], 0.f);
        float h3v = fmaxf(c[3] + bias[64 + col + 1], 0.f);
        uint2 hiA, loA;
        split4(make_float4(h0, h1v, h2v, h3v), hiA, loA);
        *(uint32_t*)(smc + FA_HI + myrow * 144 + col * 2) = hiA.x;
        *(uint32_t*)(smc + FA_LO + myrow * 144 + col * 2) = loA.x;
        *(uint32_t*)(smc + FA_HI + (myrow + 8) * 144 + col * 2) = hiA.y;
        *(uint32_t*)(smc + FA_LO + (myrow + 8) * 144 + col * 2) = loA.y;
    }
    __syncthreads();

#pragma unroll
    for (int kt = 0; kt < 4; kt++) {
        uint32_t off = (uint32_t)(arow * 144 + kt * 32 + acolB);
        ldsm_x4(a2h[kt], sbase + FA_HI + off);
        ldsm_x4(a2l[kt], sbase + FA_LO + off);
    }

    // Phase 2: out = h1@Wc1 + h2@Wc2 + bc
#pragma unroll
    for (int nt = 0; nt < 8; nt++) {
        uint32_t b1h[4][2], b1l[4][2], b2h[4][2], b2l[4][2];
#pragma unroll
        for (int kt = 0; kt < 4; kt++) {
            uint32_t ba = (uint32_t)((nt * 8 + brow) * 144 + kt * 32 + bkB);
            ldsm_x2(b1h[kt], sbase + FB_BASE + 4 * 9216 + ba);
            ldsm_x2(b1l[kt], sbase + FB_BASE + 5 * 9216 + ba);
            ldsm_x2(b2h[kt], sbase + FB_BASE + 6 * 9216 + ba);
            ldsm_x2(b2l[kt], sbase + FB_BASE + 7 * 9216 + ba);
        }
        float c[4] = {0.f, 0.f, 0.f, 0.f};
#pragma unroll
        for (int kt = 0; kt < 4; kt++) {
            mma_bf16(c, a1h[kt], b1h[kt]);
            mma_bf16(c, a1h[kt], b1l[kt]);
            mma_bf16(c, a1l[kt], b1h[kt]);
            mma_bf16(c, a2h[kt], b2h[kt]);
            mma_bf16(c, a2h[kt], b2l[kt]);
            mma_bf16(c, a2l[kt], b2h[kt]);
        }
        int col = nt * 8 + 2 * tig;
        int gr1 = row0 + myrow;
        int gr2 = gr1 + 8;
        if (gr1 < Nn)
            *(float2*)(out + (size_t)gr1 * 64 + col) =
                make_float2(c[0] + bias[128 + col], c[1] + bias[128 + col + 1]);
        if (gr2 < Nn)
            *(float2*)(out + (size_t)gr2 * 64 + col) =
                make_float2(c[2] + bias[128 + col], c[3] + bias[128 + col + 1]);
    }
}

// ---------------------------------------------------------------------------
extern "C" void kernel_launch(void* const* d_in, const int* in_sizes, int n_in,
                              void* d_out, int out_size)
{
    const float* x     = (const float*)d_in[0];
    const float* e     = (const float*)d_in[1];
    const int*   ei    = (const int*)d_in[2];
    const float* attr1 = (const float*)d_in[3];
    const float* nc1   = (const float*)d_in[4];
    const int*   x_idx = (const int*)d_in[5];
    const float* eps1  = (const float*)d_in[6];
    const float* eps2  = (const float*)d_in[7];
    const float* W_ma  = (const float*)d_in[8];
    const float* b_ma  = (const float*)d_in[9];
    const float* W_mu  = (const float*)d_in[10];
    const float* b_mu  = (const float*)d_in[11];
    const float* W_ua  = (const float*)d_in[12];
    const float* b_ua  = (const float*)d_in[13];
    const float* W_uu  = (const float*)d_in[14];
    const float* b_uu  = (const float*)d_in[15];
    const float* W_c   = (const float*)d_in[16];
    const float* b_c   = (const float*)d_in[17];
    float* out = (float*)d_out;

    cudaFuncSetAttribute(k_pre_fused,  cudaFuncAttributeMaxDynamicSharedMemorySize, SM_NP_TOT);
    cudaFuncSetAttribute(k_upagg_hmma, cudaFuncAttributeMaxDynamicSharedMemorySize, SM_UPG_TOT);
    cudaFuncSetAttribute(k_edge_hmma,  cudaFuncAttributeMaxDynamicSharedMemorySize, SM_EDGE_TOT);
    cudaFuncSetAttribute(k_final_hmma, cudaFuncAttributeMaxDynamicSharedMemorySize, SM_FIN_TOT);

    // merged weight prep (+ msgupB padding zeros)
    k_prep_all<<<(Bb * 64 * 12 + 255) / 256, 256>>>(W_ma, W_ua, W_uu, W_c, W_mu);

    // fat kernel: node_pre + mlp->split
    k_pre_fused<<<NODE_BLKS + MLP_BLKS, 256, SM_NP_TOT>>>(x, eps1, b_ma,
                                                          attr1, b_mu);

    // cluster aggregation (HMMA)
    k_upagg_hmma<<<dim3(8, Bb), 256, SM_UPG_TOT>>>(nc1);

    // edge kernel (HMMA, M=256 tiles, merged B ldsm, red.v4)
    k_edge_hmma<<<Ee / 256, 256, SM_EDGE_TOT>>>(e, ei);

    // fused tail (HMMA)
    k_final_hmma<<<(Nn + 127) / 128, 256, SM_FIN_TOT>>>(x, x_idx, eps2,
                                                        b_ua, b_uu, b_c, out);
}